// round 7
// baseline (speedup 1.0000x reference)
#include <cuda_runtime.h>

// B-spline layer, single fused kernel, max-residency version.
// out[b,f] = ((q3*u+q2)*u+q1)*u + q0,  u = 55x - ii, ii = floor(55x) in [0,54],
// q_d[ii,f] = sum_r P[ii][r][d] * C[ii+3+r, f]   (bias folded into q0).
// P = Cox-de Boor basis polynomial coefficients in local coord u, computed on
// the HOST in double (knot-only, deterministic), passed in the const bank.
//
// 256 thr/block, <=32 regs -> 8 blocks/SM = 2048 thr/SM. smem = 28 KB table
// only (fold reads C straight from L2). Grid (128,8): block folds once, then
// streams 32 batch rows with 4-deep load batching.

#define NF 256
#define NBATCH 4096
#define NII 55
#define NTHREADS 256

struct PTab { float p[NII][4][4]; };

// ---------------- host-side knot/coefficient math (double) ----------------
static double knotD_h(int idx) {
    if (idx < 6)  return -0.002 + 0.0005 * (double)(idx - 3);
    if (idx > 61) return 1.001  + 0.0005 * (double)(idx - 62);
    return (double)(idx - 6) / 55.0;
}

static void make_ptab(PTab& T) {
    for (int ii = 0; ii < NII; ++ii) {
        const int j = ii + 6;
        double P[4][4] = {};
        P[0][0] = 1.0;
        const double x0 = (double)ii / 55.0;
        const double bs = 1.0 / 55.0;   // x = x0 + bs*u
        for (int k = 1; k <= 3; ++k) {
            double Q[4][4] = {};
            for (int r = 0; r <= k; ++r) {
                const int i = j - k + r;
                if (r >= 1) {
                    const double inv = 1.0 / (knotD_h(i + k) - knotD_h(i));
                    const double a = (x0 - knotD_h(i)) * inv;
                    const double b = bs * inv;
                    for (int d = 0; d < 4; ++d) {
                        Q[r][d] += a * P[r - 1][d];
                        if (d > 0) Q[r][d] += b * P[r - 1][d - 1];
                    }
                }
                if (r <= k - 1) {
                    const double inv = 1.0 / (knotD_h(i + k + 1) - knotD_h(i + 1));
                    const double a = (knotD_h(i + k + 1) - x0) * inv;
                    const double b = -bs * inv;
                    for (int d = 0; d < 4; ++d) {
                        Q[r][d] += a * P[r][d];
                        if (d > 0) Q[r][d] += b * P[r][d - 1];
                    }
                }
            }
            for (int r = 0; r < 4; ++r)
                for (int d = 0; d < 4; ++d) P[r][d] = Q[r][d];
        }
        for (int r = 0; r < 4; ++r)
            for (int d = 0; d < 4; ++d) T.p[ii][r][d] = (float)P[r][d];
    }
}

// --------------------------------- kernel ---------------------------------
__global__ __launch_bounds__(NTHREADS, 8) void BSL_25898652795515_kernel(
    const PTab T,                     // 3.5 KB const bank
    const float* __restrict__ X,      // (4096, 256)
    const float* __restrict__ C,      // (64, 256)
    const float* __restrict__ bias,   // (256,)
    float* __restrict__ out)          // (4096, 256)
{
    __shared__ float4 sT[NII * 32];   // 28 KB folded coefficient tile

    const int f0   = blockIdx.y * 32;
    const int row0 = blockIdx.x * 32;
    const int tid  = threadIdx.x;
    const int lane = tid & 31;
    const int wrp  = tid >> 5;        // 0..7
    const int f    = f0 + lane;

    // ---- fold: sT[ii*32+ln].d = sum_r P[ii][r][d] * C[(ii+3+r)*NF + f0+ln]
    // ii = o>>5 warp-uniform -> P reads take the uniform (LDCU) const port.
    // 4 coalesced, mutually independent LDGs per element -> deep MLP.
    for (int o = tid; o < NII * 32; o += NTHREADS) {
        const int ii = o >> 5;
        const int ln = o & 31;
        const float c0 = __ldg(&C[(ii + 3) * NF + f0 + ln]);
        const float c1 = __ldg(&C[(ii + 4) * NF + f0 + ln]);
        const float c2 = __ldg(&C[(ii + 5) * NF + f0 + ln]);
        const float c3 = __ldg(&C[(ii + 6) * NF + f0 + ln]);
        float4 q;
        q.x = fmaf(T.p[ii][0][0], c0, fmaf(T.p[ii][1][0], c1,
              fmaf(T.p[ii][2][0], c2, fmaf(T.p[ii][3][0], c3,
              __ldg(&bias[f0 + ln])))));
        q.y = fmaf(T.p[ii][0][1], c0, fmaf(T.p[ii][1][1], c1,
              fmaf(T.p[ii][2][1], c2, T.p[ii][3][1] * c3)));
        q.z = fmaf(T.p[ii][0][2], c0, fmaf(T.p[ii][1][2], c1,
              fmaf(T.p[ii][2][2], c2, T.p[ii][3][2] * c3)));
        q.w = fmaf(T.p[ii][0][3], c0, fmaf(T.p[ii][1][3], c1,
              fmaf(T.p[ii][2][3], c2, T.p[ii][3][3] * c3)));
        sT[o] = q;
    }
    __syncthreads();

    // ---- stream 32 rows: 4 rows/thread, all loads batched (MLP = 4) ----
    float xv[4];
    #pragma unroll
    for (int k = 0; k < 4; ++k)
        xv[k] = X[(row0 + k * 8 + wrp) * NF + f];

    #pragma unroll
    for (int k = 0; k < 4; ++k) {
        const float xs = xv[k] * 55.0f;
        int ii = min((int)xs, 54);    // x >= 0 -> trunc == floor
        const float u = xs - (float)ii;
        // LDS.128: bank = (ii*128 + 4*lane) % 32 = 4*lane % 32 -> conflict-free
        const float4 c = sT[ii * 32 + lane];
        out[(row0 + k * 8 + wrp) * NF + f] =
            fmaf(fmaf(fmaf(c.w, u, c.z), u, c.y), u, c.x);
    }
}

extern "C" void kernel_launch(void* const* d_in, const int* in_sizes, int n_in,
                              void* d_out, int out_size) {
    const float* x    = (const float*)d_in[0];   // (4096, 256)
    const float* ctrl = (const float*)d_in[1];   // (64, 256)
    const float* bias = (const float*)d_in[2];   // (256,)
    float* out = (float*)d_out;

    PTab T;
    make_ptab(T);   // host double math, knot-only, deterministic

    dim3 grid(NBATCH / 32, NF / 32);   // (128, 8) = 1024 blocks, ~7/SM, 1 wave
    BSL_25898652795515_kernel<<<grid, NTHREADS>>>(T, x, ctrl, bias, out);
}

// round 8
// speedup vs baseline: 1.7179x; 1.7179x over previous
#include <cuda_runtime.h>

// B-spline layer, two kernels overlapped via Programmatic Dependent Launch:
//  K1 (fold): g_tab[ii][f] = sum_r P[ii][r][d] * C[ii+3+r, f]  (+bias in q0)
//  K2 (main): out[b,f] = ((q3*u+q2)*u+q1)*u+q0, u = 55x-ii, ii = floor(55x).
// K2 launches concurrently with K1 (PDL), prefetches X (independent of K1),
// then cudaGridDependencySynchronize() before reading g_tab.
// P = Cox-de Boor basis polynomial coefficients in local coord u, computed on
// the HOST in double (knot-only, deterministic), passed in the const bank.

#define NF 256
#define NBATCH 4096
#define NII 55
#define ROWS_PER_BLOCK 64
#define K2_THREADS 512

struct PTab { float p[NII][4][4]; };

// [tile 8][ii 55][lane 32] float4 (q0+bias, q1, q2, q3) — 225 KB, L2-resident.
__device__ float4 g_tab[8 * NII * 32];

// ---------------- host-side knot/coefficient math (double) ----------------
static double knotD_h(int idx) {
    if (idx < 6)  return -0.002 + 0.0005 * (double)(idx - 3);
    if (idx > 61) return 1.001  + 0.0005 * (double)(idx - 62);
    return (double)(idx - 6) / 55.0;
}

static void make_ptab(PTab& T) {
    for (int ii = 0; ii < NII; ++ii) {
        const int j = ii + 6;
        double P[4][4] = {};
        P[0][0] = 1.0;
        const double x0 = (double)ii / 55.0;
        const double bs = 1.0 / 55.0;   // x = x0 + bs*u
        for (int k = 1; k <= 3; ++k) {
            double Q[4][4] = {};
            for (int r = 0; r <= k; ++r) {
                const int i = j - k + r;
                if (r >= 1) {
                    const double inv = 1.0 / (knotD_h(i + k) - knotD_h(i));
                    const double a = (x0 - knotD_h(i)) * inv;
                    const double b = bs * inv;
                    for (int d = 0; d < 4; ++d) {
                        Q[r][d] += a * P[r - 1][d];
                        if (d > 0) Q[r][d] += b * P[r - 1][d - 1];
                    }
                }
                if (r <= k - 1) {
                    const double inv = 1.0 / (knotD_h(i + k + 1) - knotD_h(i + 1));
                    const double a = (knotD_h(i + k + 1) - x0) * inv;
                    const double b = -bs * inv;
                    for (int d = 0; d < 4; ++d) {
                        Q[r][d] += a * P[r][d];
                        if (d > 0) Q[r][d] += b * P[r][d - 1];
                    }
                }
            }
            for (int r = 0; r < 4; ++r)
                for (int d = 0; d < 4; ++d) P[r][d] = Q[r][d];
        }
        for (int r = 0; r < 4; ++r)
            for (int d = 0; d < 4; ++d) T.p[ii][r][d] = (float)P[r][d];
    }
}

// ------------------------------ K1: fold -----------------------------------
__global__ __launch_bounds__(256) void BSL_fold(
    const PTab T,
    const float* __restrict__ C,      // (64, 256)
    const float* __restrict__ bias)   // (256,)
{
    const int ii = blockIdx.x;        // 0..54 (warp-uniform -> P reads = LDC)
    const int f  = threadIdx.x;       // 0..255
    const float c0 = C[(ii + 3) * NF + f];
    const float c1 = C[(ii + 4) * NF + f];
    const float c2 = C[(ii + 5) * NF + f];
    const float c3 = C[(ii + 6) * NF + f];
    float4 q;
    q.x = T.p[ii][0][0]*c0 + T.p[ii][1][0]*c1 + T.p[ii][2][0]*c2 + T.p[ii][3][0]*c3
        + bias[f];
    q.y = T.p[ii][0][1]*c0 + T.p[ii][1][1]*c1 + T.p[ii][2][1]*c2 + T.p[ii][3][1]*c3;
    q.z = T.p[ii][0][2]*c0 + T.p[ii][1][2]*c1 + T.p[ii][2][2]*c2 + T.p[ii][3][2]*c3;
    q.w = T.p[ii][0][3]*c0 + T.p[ii][1][3]*c1 + T.p[ii][2][3]*c2 + T.p[ii][3][3]*c3;
    g_tab[((f >> 5) * NII + ii) * 32 + (f & 31)] = q;
    // implicit programmatic completion at kernel end
}

// ------------------------------ K2: main -----------------------------------
__global__ __launch_bounds__(K2_THREADS) void BSL_25898652795515_kernel(
    const float* __restrict__ X,      // (4096, 256)
    float* __restrict__ out)          // (4096, 256)
{
    __shared__ float4 sT[NII * 32];   // 28 KB folded coefficient tile

    const int tile = blockIdx.y;
    const int row0 = blockIdx.x * ROWS_PER_BLOCK;
    const int tid  = threadIdx.x;
    const int lane = tid & 31;
    const int wrp  = tid >> 5;        // 0..15
    const int f    = tile * 32 + lane;

    // Prefetch X — independent of K1, overlaps K1's execution under PDL.
    float xv[4];
    #pragma unroll
    for (int it = 0; it < 4; ++it)
        xv[it] = X[(row0 + it * 16 + wrp) * NF + f];

    // Wait for K1's g_tab writes to be visible.
#if __CUDA_ARCH__ >= 900
    cudaGridDependencySynchronize();
#endif

    // Copy folded table tile (L2 resident after K1): 28 KB, LDG.128/STS.128
    #pragma unroll
    for (int idx = tid; idx < NII * 32; idx += K2_THREADS)
        sT[idx] = g_tab[tile * (NII * 32) + idx];
    __syncthreads();

    #pragma unroll
    for (int it = 0; it < 4; ++it) {
        const float xs = xv[it] * 55.0f;
        int ii = (int)xs;             // x >= 0 -> trunc == floor
        ii = min(ii, 54);
        const float u = xs - (float)ii;
        // conflict-free LDS.128: ii stride = 512 B (multiple of 32 banks)
        const float4 c = sT[ii * 32 + lane];
        out[(row0 + it * 16 + wrp) * NF + f] =
            fmaf(fmaf(fmaf(c.w, u, c.z), u, c.y), u, c.x);
    }
}

extern "C" void kernel_launch(void* const* d_in, const int* in_sizes, int n_in,
                              void* d_out, int out_size) {
    const float* x    = (const float*)d_in[0];   // (4096, 256)
    const float* ctrl = (const float*)d_in[1];   // (64, 256)
    const float* bias = (const float*)d_in[2];   // (256,)
    float* out = (float*)d_out;

    PTab T;
    make_ptab(T);   // host double math, knot-only, deterministic

    BSL_fold<<<NII, 256>>>(T, ctrl, bias);

    // K2 with Programmatic Dependent Launch: may begin while K1 runs; the
    // device-side cudaGridDependencySynchronize() enforces the data dependency.
    cudaLaunchConfig_t cfg = {};
    cfg.gridDim  = dim3(NBATCH / ROWS_PER_BLOCK, NF / 32, 1);   // (64, 8)
    cfg.blockDim = dim3(K2_THREADS, 1, 1);
    cfg.dynamicSmemBytes = 0;
    cfg.stream = 0;   // legacy default stream (same one the harness captures)
    cudaLaunchAttribute attr[1];
    attr[0].id = cudaLaunchAttributeProgrammaticStreamSerialization;
    attr[0].val.programmaticStreamSerializationAllowed = 1;
    cfg.attrs = attr;
    cfg.numAttrs = 1;
    cudaError_t e = cudaLaunchKernelEx(&cfg, BSL_25898652795515_kernel, x, out);
    if (e != cudaSuccess) {
        // Fallback: plain serialized launch (still correct).
        dim3 grid(NBATCH / ROWS_PER_BLOCK, NF / 32);
        BSL_25898652795515_kernel<<<grid, K2_THREADS>>>(x, out);
    }
}